// round 5
// baseline (speedup 1.0000x reference)
#include <cuda_runtime.h>
#include <cstdint>
#include <math.h>

#define KSEL 100
#define NTHREADS 256
#define CAND_MAX 512
#define COMP_MAX 4096
#define SAMPLE_NUM 10

__device__ __forceinline__ uint32_t f2key(float f) {
    uint32_t u = __float_as_uint(f);
    return (u & 0x80000000u) ? ~u : (u | 0x80000000u);
}

// warp-0 suffix-scan over 256 bins + select bin containing the rem-th largest.
// Must be called by all 256 threads between __syncthreads() pairs by caller.
__device__ __forceinline__ void scan_select(int* sHist, uint32_t* sPrefix,
                                            int* sRem, int shift, int tid) {
    if (tid < 32) {
        int h[8];
        #pragma unroll
        for (int j = 0; j < 8; j++) h[j] = sHist[tid * 8 + j];
        int csum = 0;
        #pragma unroll
        for (int j = 0; j < 8; j++) csum += h[j];
        int suf = csum;
        #pragma unroll
        for (int d = 1; d < 32; d <<= 1) {
            int v = __shfl_down_sync(0xffffffffu, suf, d);
            if (tid + d < 32) suf += v;
        }
        int add = suf - csum;          // sum of chunks above this lane
        int S[8]; int acc = add;
        #pragma unroll
        for (int j = 7; j >= 0; j--) { acc += h[j]; S[j] = acc; }
        int rem = *sRem;
        __syncwarp();
        #pragma unroll
        for (int j = 0; j < 8; j++) {
            int Snext = (j == 7) ? add : S[j + 1];
            if (S[j] >= rem && Snext < rem) {
                *sPrefix |= ((uint32_t)(tid * 8 + j)) << shift;
                *sRem = rem - Snext;
            }
        }
    }
}

__global__ __launch_bounds__(NTHREADS) void postprocess_kernel(
    const float* __restrict__ blk_logits,
    const float* __restrict__ lin_logits,
    const float* __restrict__ chr_logits,
    const float* __restrict__ blk_raw,
    const float* __restrict__ lin_raw,
    const float* __restrict__ chr_raw,
    const float* __restrict__ tsizes,
    float* __restrict__ out)
{
    extern __shared__ unsigned long long sComp[];   // COMP_MAX entries (32KB)
    __shared__ int       sHist[256];
    __shared__ unsigned long long sCand[CAND_MAX];
    __shared__ int       sCompCnt, sCandCnt;
    __shared__ uint32_t  sPrefix;
    __shared__ int       sRem;
    __shared__ float     sVal[KSEL];
    __shared__ int       sIdx[KSEL];
    __shared__ float     sData[KSEL * 16];
    __shared__ float     sBox[KSEL * 4];
    __shared__ float     sArea[KSEL];
    __shared__ int       sKeep[KSEL];
    __shared__ float     sBelong[KSEL];
    __shared__ int       sFb;

    const int b     = blockIdx.x;
    const int level = blockIdx.y;
    const int tid   = threadIdx.x;
    const int lane  = tid & 31;

    const float* logits;
    const float* raw;
    const float* parent = nullptr;
    int N, parentN = 0, ef = 1;
    bool bez = false;
    int data_off, score_off, keep_off, dd;

    if (level == 0) {
        logits = blk_logits; raw = blk_raw; N = 4096; dd = 4;
        data_off = 0;      score_off = 25600;  keep_off = 32000;
    } else if (level == 1) {
        logits = lin_logits; raw = lin_raw; parent = blk_raw; parentN = 4096; ef = 4;
        N = 16384; dd = 4;
        data_off = 38400;  score_off = 64000;  keep_off = 70400;
    } else {
        logits = chr_logits; raw = chr_raw; parent = lin_raw; parentN = 16384; ef = 1;
        N = 16384; dd = 16; bez = true;
        data_off = 76800;  score_off = 179200; keep_off = 185600;
    }

    const float img_h = tsizes[2 * b + 0];
    const float img_w = tsizes[2 * b + 1];
    const float* lg = logits + (size_t)b * N;

    // ---- pass 0: warp-aggregated histogram on top byte ----
    sHist[tid] = 0;
    if (tid == 0) { sRem = KSEL; sPrefix = 0u; sCompCnt = 0; sCandCnt = 0; }
    __syncthreads();
    for (int i = tid; i < N; i += NTHREADS) {           // N % 256 == 0: full warps
        int bin = (int)(f2key(lg[i]) >> 24);
        unsigned mask = __match_any_sync(0xffffffffu, bin);
        if (lane == __ffs(mask) - 1)
            atomicAdd(&sHist[bin], __popc(mask));
    }
    __syncthreads();
    scan_select(sHist, &sPrefix, &sRem, 24, tid);
    __syncthreads();
    const uint32_t b0 = sPrefix >> 24;

    // ---- compact keys with top byte >= b0 (warp-aggregated positions) ----
    for (int i = tid; i < N; i += NTHREADS) {
        uint32_t kk = f2key(lg[i]);
        bool pred = (kk >> 24) >= b0;
        unsigned m = __ballot_sync(0xffffffffu, pred);
        if (m) {
            int leader = __ffs(m) - 1;
            int base = 0;
            if (lane == leader) base = atomicAdd(&sCompCnt, __popc(m));
            base = __shfl_sync(0xffffffffu, base, leader);
            if (pred) {
                int pos = base + __popc(m & ((1u << lane) - 1));
                if (pos < COMP_MAX)
                    sComp[pos] = ((unsigned long long)kk << 32) |
                                 (unsigned long long)(0xFFFFFFFFu - (uint32_t)i);
            }
        }
    }
    __syncthreads();
    const int  Mtot = sCompCnt;
    const bool ovf  = Mtot > COMP_MAX;
    const int  M    = ovf ? 0 : Mtot;

    // ---- passes 1..3 over the compacted list (or global on overflow) ----
    #pragma unroll
    for (int pass = 1; pass < 4; pass++) {
        const int shift = 24 - 8 * pass;
        const uint32_t hi_mask = 0xFFFFFFFFu << (shift + 8);
        sHist[tid] = 0;
        __syncthreads();
        const uint32_t pref = sPrefix;
        if (!ovf) {
            for (int i = tid; i < M; i += NTHREADS) {
                uint32_t kk = (uint32_t)(sComp[i] >> 32);
                if ((kk & hi_mask) == pref)
                    atomicAdd(&sHist[(kk >> shift) & 0xFF], 1);
            }
        } else {
            for (int i = tid; i < N; i += NTHREADS) {
                uint32_t kk = f2key(lg[i]);
                if ((kk & hi_mask) == pref)
                    atomicAdd(&sHist[(kk >> shift) & 0xFF], 1);
            }
        }
        __syncthreads();
        scan_select(sHist, &sPrefix, &sRem, shift, tid);
        __syncthreads();
    }
    const uint32_t T = sPrefix;

    // ---- collect candidates >= T ----
    if (!ovf) {
        for (int i = tid; i < M; i += NTHREADS) {
            unsigned long long e = sComp[i];
            if ((uint32_t)(e >> 32) >= T) {
                int pos = atomicAdd(&sCandCnt, 1);
                if (pos < CAND_MAX) sCand[pos] = ~e;
            }
        }
    } else {
        for (int i = tid; i < N; i += NTHREADS) {
            uint32_t kk = f2key(lg[i]);
            if (kk >= T) {
                int pos = atomicAdd(&sCandCnt, 1);
                if (pos < CAND_MAX)
                    sCand[pos] = ~(((unsigned long long)kk << 32) |
                                   (unsigned long long)(0xFFFFFFFFu - (uint32_t)i));
            }
        }
    }
    __syncthreads();
    const int cnt = min(sCandCnt, CAND_MAX);
    int M2 = 128;
    while (M2 < cnt) M2 <<= 1;                          // 128 / 256 / 512
    for (int i = cnt + tid; i < M2; i += NTHREADS)
        sCand[i] = 0xFFFFFFFFFFFFFFFFull;               // sorts last
    __syncthreads();

    // ---- bitonic sort M2 elements ascending ----
    for (int size2 = 2; size2 <= M2; size2 <<= 1) {
        for (int stride = size2 >> 1; stride > 0; stride >>= 1) {
            __syncthreads();
            if (tid < (M2 >> 1)) {
                int pos = ((tid & ~(stride - 1)) << 1) | (tid & (stride - 1));
                bool up = ((pos & size2) == 0);
                unsigned long long a = sCand[pos];
                unsigned long long c = sCand[pos + stride];
                if ((a > c) == up) { sCand[pos] = c; sCand[pos + stride] = a; }
            }
        }
    }
    __syncthreads();

    // ---- decode top-100 ----
    if (tid < KSEL) {
        unsigned long long comb = ~sCand[tid];
        uint32_t kk  = (uint32_t)(comb >> 32);
        uint32_t idx = 0xFFFFFFFFu - (uint32_t)(comb & 0xFFFFFFFFull);
        sIdx[tid] = (int)idx;
        uint32_t u = (kk & 0x80000000u) ? (kk & 0x7FFFFFFFu) : ~kk;
        float lv = __uint_as_float(u);
        sVal[tid] = 1.0f / (1.0f + expf(-lv));
    }

    // ---- boxes / data ----
    if (tid < KSEL) {
        int si = sIdx[tid];
        if (!bez) {
            const float* r = raw + ((size_t)b * N + si) * 4;
            float cx = r[0], cy = r[1], w = r[2], h = r[3];
            float x1 = (cx - 0.5f * w) * img_w;
            float y1 = (cy - 0.5f * h) * img_h;
            float x2 = (cx + 0.5f * w) * img_w;
            float y2 = (cy + 0.5f * h) * img_h;
            if (level == 0) {
                x1 = fminf(fmaxf(x1, 0.0f), img_w);
                y1 = fminf(fmaxf(y1, 0.0f), img_h);
                x2 = fminf(fmaxf(x2, 0.0f), img_w);
                y2 = fminf(fmaxf(y2, 0.0f), img_h);
            }
            sData[tid * 16 + 0] = x1; sData[tid * 16 + 1] = y1;
            sData[tid * 16 + 2] = x2; sData[tid * 16 + 3] = y2;
            sBox[tid * 4 + 0] = x1; sBox[tid * 4 + 1] = y1;
            sBox[tid * 4 + 2] = x2; sBox[tid * 4 + 3] = y2;
            sArea[tid] = (x2 - x1) * (y2 - y1);
        } else {
            const float* r = raw + ((size_t)b * N + si) * 16;
            float cp0[8], cp1[8];
            #pragma unroll
            for (int f = 0; f < 8; f++) {
                cp0[f] = r[2 * f + 0] * img_h;          // scale_pts = tile((h,w),8)
                cp1[f] = r[2 * f + 1] * img_w;
                sData[tid * 16 + 2 * f + 0] = cp0[f];
                sData[tid * 16 + 2 * f + 1] = cp1[f];
            }
            float mn0 =  INFINITY, mn1 =  INFINITY;
            float mx0 = -INFINITY, mx1 = -INFINITY;
            #pragma unroll
            for (int s = 0; s < SAMPLE_NUM; s++) {
                float t  = (float)s / (float)(SAMPLE_NUM - 1);
                float ti = 1.0f - t;
                float b0c = ti * ti * ti;
                float b1c = 3.0f * t * ti * ti;
                float b2c = 3.0f * t * t * ti;
                float b3c = t * t * t;
                float px = b0c * cp0[0] + b1c * cp0[1] + b2c * cp0[2] + b3c * cp0[3];
                float py = b0c * cp1[0] + b1c * cp1[1] + b2c * cp1[2] + b3c * cp1[3];
                float qx = b0c * cp0[4] + b1c * cp0[5] + b2c * cp0[6] + b3c * cp0[7];
                float qy = b0c * cp1[4] + b1c * cp1[5] + b2c * cp1[6] + b3c * cp1[7];
                mn0 = fminf(mn0, fminf(px, qx));
                mn1 = fminf(mn1, fminf(py, qy));
                mx0 = fmaxf(mx0, fmaxf(px, qx));
                mx1 = fmaxf(mx1, fmaxf(py, qy));
            }
            sBox[tid * 4 + 0] = mn0; sBox[tid * 4 + 1] = mn1;
            sBox[tid * 4 + 2] = mx0; sBox[tid * 4 + 3] = mx1;
            sArea[tid] = (mx0 - mn0) * (mx1 - mn1);
        }
    }

    // ---- keep = vals > 0.1 (fallback to index 0) ----
    int keep0 = (tid < KSEL) ? (sVal[tid] > 0.1f ? 1 : 0) : 0;
    int any0 = __syncthreads_or(keep0);
    if (tid < KSEL) sKeep[tid] = any0 ? keep0 : (tid == 0 ? 1 : 0);

    // ---- parent belong filter (line / char) ----
    if (level > 0) {
        int valid = 0, mykeep = 0;
        if (tid < KSEL) {
            mykeep = sKeep[tid];
            int pi = sIdx[tid] / ef;
            const float* pr = parent + ((size_t)b * parentN + pi) * 4;
            float pcx = pr[0], pcy = pr[1], pw = pr[2], ph = pr[3];
            float px1 = (pcx - 0.5f * pw) * img_w;
            float py1 = (pcy - 0.5f * ph) * img_h;
            float px2 = (pcx + 0.5f * pw) * img_w;
            float py2 = (pcy + 0.5f * ph) * img_h;
            float bx1 = sBox[tid * 4 + 0], by1 = sBox[tid * 4 + 1];
            float bx2 = sBox[tid * 4 + 2], by2 = sBox[tid * 4 + 3];
            float ix1 = fmaxf(bx1, px1), iy1 = fmaxf(by1, py1);
            float ix2 = fminf(bx2, px2), iy2 = fminf(by2, py2);
            float inter = fmaxf(ix2 - ix1, 0.0f) * fmaxf(iy2 - iy1, 0.0f);
            float carea = (bx2 - bx1) * (by2 - by1);
            float belong = inter / (carea + 1e-6f);
            sBelong[tid] = belong;
            valid = (belong > 0.6f) ? 1 : 0;
        }
        int haveValid = __syncthreads_or(valid && mykeep);
        if (!haveValid) {
            if (tid == 0) {
                float best = -INFINITY; int bi = 0;
                for (int kk = 0; kk < KSEL; kk++) {
                    float v = sKeep[kk] ? sBelong[kk] : -INFINITY;
                    if (v > best) { best = v; bi = kk; }
                }
                sFb = bi;
            }
            __syncthreads();
            if (tid < KSEL) valid = (tid == sFb) ? 1 : 0;
        }
        if (tid < KSEL) sKeep[tid] &= valid;
    }
    __syncthreads();

    // ---- greedy NMS: warp 0, register-resident, no block barriers ----
    if (tid < 32) {
        float x1r[4], y1r[4], x2r[4], y2r[4], arr[4]; int kp[4];
        #pragma unroll
        for (int s = 0; s < 4; s++) {
            int idx = tid + 32 * s;
            if (idx < KSEL) {
                x1r[s] = sBox[idx * 4 + 0]; y1r[s] = sBox[idx * 4 + 1];
                x2r[s] = sBox[idx * 4 + 2]; y2r[s] = sBox[idx * 4 + 3];
                arr[s] = sArea[idx];        kp[s]  = sKeep[idx];
            } else {
                x1r[s] = 0.f; y1r[s] = 0.f; x2r[s] = 0.f; y2r[s] = 0.f;
                arr[s] = 0.f; kp[s] = 0;
            }
        }
        #pragma unroll
        for (int slot = 0; slot < 4; slot++) {
            const int lim = (slot < 3) ? 32 : (KSEL - 96);
            for (int o = 0; o < lim; o++) {
                int   ki  = __shfl_sync(0xffffffffu, kp[slot],  o);
                float ix1 = __shfl_sync(0xffffffffu, x1r[slot], o);
                float iy1 = __shfl_sync(0xffffffffu, y1r[slot], o);
                float ix2 = __shfl_sync(0xffffffffu, x2r[slot], o);
                float iy2 = __shfl_sync(0xffffffffu, y2r[slot], o);
                float iar = __shfl_sync(0xffffffffu, arr[slot], o);
                if (ki) {
                    int i = slot * 32 + o;
                    #pragma unroll
                    for (int s = 0; s < 4; s++) {
                        int idx = tid + 32 * s;
                        if (idx > i && idx < KSEL && kp[s]) {
                            float tx1 = fmaxf(ix1, x1r[s]);
                            float ty1 = fmaxf(iy1, y1r[s]);
                            float tx2 = fminf(ix2, x2r[s]);
                            float ty2 = fminf(iy2, y2r[s]);
                            float inter = fmaxf(tx2 - tx1, 0.0f) * fmaxf(ty2 - ty1, 0.0f);
                            float iou = inter / (iar + arr[s] - inter);
                            if (iou > 0.1f) kp[s] = 0;
                        }
                    }
                }
            }
        }
        #pragma unroll
        for (int s = 0; s < 4; s++) {
            int idx = tid + 32 * s;
            if (idx < KSEL) sKeep[idx] = kp[s];
        }
    }
    __syncthreads();

    // ---- write outputs ----
    if (tid < KSEL) {
        const int nk = sKeep[tid];
        for (int j = 0; j < dd; j++)
            out[data_off + ((size_t)b * KSEL + tid) * dd + j] =
                nk ? sData[tid * 16 + j] : 0.0f;
        out[score_off + (size_t)b * KSEL + tid] = nk ? sVal[tid] : 0.0f;
        out[keep_off  + (size_t)b * KSEL + tid] = nk ? 1.0f : 0.0f;
    }
}

extern "C" void kernel_launch(void* const* d_in, const int* in_sizes, int n_in,
                              void* d_out, int out_size) {
    const float* blk_logits = (const float*)d_in[0];
    const float* lin_logits = (const float*)d_in[1];
    const float* chr_logits = (const float*)d_in[2];
    const float* blk_raw    = (const float*)d_in[3];
    const float* lin_raw    = (const float*)d_in[4];
    const float* chr_raw    = (const float*)d_in[5];
    const float* tsizes     = (const float*)d_in[6];
    float* out = (float*)d_out;

    const int smem = COMP_MAX * sizeof(unsigned long long);   // 32 KB
    cudaFuncSetAttribute(postprocess_kernel,
                         cudaFuncAttributeMaxDynamicSharedMemorySize, smem);
    dim3 grid(64, 3);
    postprocess_kernel<<<grid, NTHREADS, smem>>>(
        blk_logits, lin_logits, chr_logits,
        blk_raw, lin_raw, chr_raw, tsizes, out);
}

// round 6
// speedup vs baseline: 1.2965x; 1.2965x over previous
#include <cuda_runtime.h>
#include <cstdint>
#include <math.h>

#define KSEL 100
#define NTHREADS 256
#define CAND_MAX 512
#define SAMPLE_NUM 10

__device__ __forceinline__ uint32_t f2key(float f) {
    uint32_t u = __float_as_uint(f);
    return (u & 0x80000000u) ? ~u : (u | 0x80000000u);
}

// warp-0 suffix-scan over 256 bins + select bin containing the rem-th largest.
__device__ __forceinline__ void scan_select(int* sHist, uint32_t* sPrefix,
                                            int* sRem, int shift, int tid) {
    if (tid < 32) {
        int h[8];
        #pragma unroll
        for (int j = 0; j < 8; j++) h[j] = sHist[tid * 8 + j];
        int csum = 0;
        #pragma unroll
        for (int j = 0; j < 8; j++) csum += h[j];
        int suf = csum;
        #pragma unroll
        for (int d = 1; d < 32; d <<= 1) {
            int v = __shfl_down_sync(0xffffffffu, suf, d);
            if (tid + d < 32) suf += v;
        }
        int add = suf - csum;          // sum of chunks above this lane
        int S[8]; int acc = add;
        #pragma unroll
        for (int j = 7; j >= 0; j--) { acc += h[j]; S[j] = acc; }
        int rem = *sRem;
        __syncwarp();
        #pragma unroll
        for (int j = 0; j < 8; j++) {
            int Snext = (j == 7) ? add : S[j + 1];
            if (S[j] >= rem && Snext < rem) {
                *sPrefix |= ((uint32_t)(tid * 8 + j)) << shift;
                *sRem = rem - Snext;
            }
        }
    }
}

__global__ __launch_bounds__(NTHREADS) void postprocess_kernel(
    const float* __restrict__ blk_logits,
    const float* __restrict__ lin_logits,
    const float* __restrict__ chr_logits,
    const float* __restrict__ blk_raw,
    const float* __restrict__ lin_raw,
    const float* __restrict__ chr_raw,
    const float* __restrict__ tsizes,
    float* __restrict__ out)
{
    extern __shared__ uint32_t sKeys[];          // up to 16384 keys (64KB)
    __shared__ int       sHist[256];
    __shared__ unsigned long long sCand[CAND_MAX];
    __shared__ int       sCandCnt;
    __shared__ uint32_t  sPrefix;
    __shared__ int       sRem;
    __shared__ float     sVal[KSEL];
    __shared__ int       sIdx[KSEL];
    __shared__ float     sData[KSEL * 16];
    __shared__ float     sBox[KSEL * 4];
    __shared__ float     sArea[KSEL];
    __shared__ int       sKeep[KSEL];
    __shared__ float     sBelong[KSEL];
    __shared__ int       sFb;

    const int b     = blockIdx.x;
    const int level = blockIdx.y;
    const int tid   = threadIdx.x;
    const int lane  = tid & 31;

    const float* logits;
    const float* raw;
    const float* parent = nullptr;
    int N, parentN = 0, ef = 1;
    bool bez = false;
    int data_off, score_off, keep_off, dd;

    if (level == 0) {
        logits = blk_logits; raw = blk_raw; N = 4096; dd = 4;
        data_off = 0;      score_off = 25600;  keep_off = 32000;
    } else if (level == 1) {
        logits = lin_logits; raw = lin_raw; parent = blk_raw; parentN = 4096; ef = 4;
        N = 16384; dd = 4;
        data_off = 38400;  score_off = 64000;  keep_off = 70400;
    } else {
        logits = chr_logits; raw = chr_raw; parent = lin_raw; parentN = 16384; ef = 1;
        N = 16384; dd = 16; bez = true;
        data_off = 76800;  score_off = 179200; keep_off = 185600;
    }

    const float img_h = tsizes[2 * b + 0];
    const float img_w = tsizes[2 * b + 1];
    const float* lg = logits + (size_t)b * N;

    // ---- 1. build sortable keys in shared: pure vectorized copy (high MLP) ----
    const float4* lg4 = (const float4*)lg;
    const int N4 = N >> 2;
    for (int i = tid; i < N4; i += NTHREADS) {
        float4 v = lg4[i];
        sKeys[4 * i + 0] = f2key(v.x);
        sKeys[4 * i + 1] = f2key(v.y);
        sKeys[4 * i + 2] = f2key(v.z);
        sKeys[4 * i + 3] = f2key(v.w);
    }
    sHist[tid] = 0;
    if (tid == 0) { sRem = KSEL; sPrefix = 0u; sCandCnt = 0; }
    __syncthreads();

    // ---- 2. pass 0: warp-aggregated histogram on top byte (from SMEM) ----
    for (int i = tid; i < N; i += NTHREADS) {           // N % 256 == 0: full warps
        int bin = (int)(sKeys[i] >> 24);
        unsigned mask = __match_any_sync(0xffffffffu, bin);
        if (lane == __ffs(mask) - 1)
            atomicAdd(&sHist[bin], __popc(mask));
    }
    __syncthreads();
    scan_select(sHist, &sPrefix, &sRem, 24, tid);
    __syncthreads();

    // ---- passes 1..3: plain predicated atomics (predicate rarely true) ----
    #pragma unroll
    for (int pass = 1; pass < 4; pass++) {
        const int shift = 24 - 8 * pass;
        const uint32_t hi_mask = 0xFFFFFFFFu << (shift + 8);
        sHist[tid] = 0;
        __syncthreads();
        const uint32_t pref = sPrefix;
        for (int i = tid; i < N; i += NTHREADS) {
            uint32_t kk = sKeys[i];
            if ((kk & hi_mask) == pref)
                atomicAdd(&sHist[(kk >> shift) & 0xFF], 1);
        }
        __syncthreads();
        scan_select(sHist, &sPrefix, &sRem, shift, tid);
        __syncthreads();
    }
    const uint32_t T = sPrefix;

    // ---- 3. collect candidates >= T ----
    for (int i = tid; i < N; i += NTHREADS) {
        uint32_t kk = sKeys[i];
        if (kk >= T) {
            int pos = atomicAdd(&sCandCnt, 1);
            if (pos < CAND_MAX)
                sCand[pos] = ~(((unsigned long long)kk << 32) |
                               (unsigned long long)(0xFFFFFFFFu - (uint32_t)i));
        }
    }
    __syncthreads();
    const int cnt = min(sCandCnt, CAND_MAX);
    int M2 = 128;
    while (M2 < cnt) M2 <<= 1;                          // 128 / 256 / 512
    for (int i = cnt + tid; i < M2; i += NTHREADS)
        sCand[i] = 0xFFFFFFFFFFFFFFFFull;               // sorts last
    __syncthreads();

    // ---- 4. bitonic sort M2 elements ascending ----
    for (int size2 = 2; size2 <= M2; size2 <<= 1) {
        for (int stride = size2 >> 1; stride > 0; stride >>= 1) {
            __syncthreads();
            if (tid < (M2 >> 1)) {
                int pos = ((tid & ~(stride - 1)) << 1) | (tid & (stride - 1));
                bool up = ((pos & size2) == 0);
                unsigned long long a = sCand[pos];
                unsigned long long c = sCand[pos + stride];
                if ((a > c) == up) { sCand[pos] = c; sCand[pos + stride] = a; }
            }
        }
    }
    __syncthreads();

    // ---- 5. decode top-100 ----
    if (tid < KSEL) {
        unsigned long long comb = ~sCand[tid];
        uint32_t kk  = (uint32_t)(comb >> 32);
        uint32_t idx = 0xFFFFFFFFu - (uint32_t)(comb & 0xFFFFFFFFull);
        sIdx[tid] = (int)idx;
        uint32_t u = (kk & 0x80000000u) ? (kk & 0x7FFFFFFFu) : ~kk;
        float lv = __uint_as_float(u);
        sVal[tid] = 1.0f / (1.0f + expf(-lv));
    }
    __syncthreads();

    // ---- 6. boxes / data ----
    if (tid < KSEL) {
        int si = sIdx[tid];
        if (!bez) {
            const float* r = raw + ((size_t)b * N + si) * 4;
            float cx = r[0], cy = r[1], w = r[2], h = r[3];
            float x1 = (cx - 0.5f * w) * img_w;
            float y1 = (cy - 0.5f * h) * img_h;
            float x2 = (cx + 0.5f * w) * img_w;
            float y2 = (cy + 0.5f * h) * img_h;
            if (level == 0) {
                x1 = fminf(fmaxf(x1, 0.0f), img_w);
                y1 = fminf(fmaxf(y1, 0.0f), img_h);
                x2 = fminf(fmaxf(x2, 0.0f), img_w);
                y2 = fminf(fmaxf(y2, 0.0f), img_h);
            }
            sData[tid * 16 + 0] = x1; sData[tid * 16 + 1] = y1;
            sData[tid * 16 + 2] = x2; sData[tid * 16 + 3] = y2;
            sBox[tid * 4 + 0] = x1; sBox[tid * 4 + 1] = y1;
            sBox[tid * 4 + 2] = x2; sBox[tid * 4 + 3] = y2;
            sArea[tid] = (x2 - x1) * (y2 - y1);
        } else {
            const float* r = raw + ((size_t)b * N + si) * 16;
            float cp0[8], cp1[8];
            #pragma unroll
            for (int f = 0; f < 8; f++) {
                cp0[f] = r[2 * f + 0] * img_h;          // scale_pts = tile((h,w),8)
                cp1[f] = r[2 * f + 1] * img_w;
                sData[tid * 16 + 2 * f + 0] = cp0[f];
                sData[tid * 16 + 2 * f + 1] = cp1[f];
            }
            float mn0 =  INFINITY, mn1 =  INFINITY;
            float mx0 = -INFINITY, mx1 = -INFINITY;
            #pragma unroll
            for (int s = 0; s < SAMPLE_NUM; s++) {
                float t  = (float)s / (float)(SAMPLE_NUM - 1);
                float ti = 1.0f - t;
                float b0c = ti * ti * ti;
                float b1c = 3.0f * t * ti * ti;
                float b2c = 3.0f * t * t * ti;
                float b3c = t * t * t;
                float px = b0c * cp0[0] + b1c * cp0[1] + b2c * cp0[2] + b3c * cp0[3];
                float py = b0c * cp1[0] + b1c * cp1[1] + b2c * cp1[2] + b3c * cp1[3];
                float qx = b0c * cp0[4] + b1c * cp0[5] + b2c * cp0[6] + b3c * cp0[7];
                float qy = b0c * cp1[4] + b1c * cp1[5] + b2c * cp1[6] + b3c * cp1[7];
                mn0 = fminf(mn0, fminf(px, qx));
                mn1 = fminf(mn1, fminf(py, qy));
                mx0 = fmaxf(mx0, fmaxf(px, qx));
                mx1 = fmaxf(mx1, fmaxf(py, qy));
            }
            sBox[tid * 4 + 0] = mn0; sBox[tid * 4 + 1] = mn1;
            sBox[tid * 4 + 2] = mx0; sBox[tid * 4 + 3] = mx1;
            sArea[tid] = (mx0 - mn0) * (mx1 - mn1);
        }
    }

    // ---- 7. keep = vals > 0.1 (fallback to index 0) ----
    int keep0 = (tid < KSEL) ? (sVal[tid] > 0.1f ? 1 : 0) : 0;
    int any0 = __syncthreads_or(keep0);
    if (tid < KSEL) sKeep[tid] = any0 ? keep0 : (tid == 0 ? 1 : 0);

    // ---- 8. parent belong filter (line / char) ----
    if (level > 0) {
        int valid = 0, mykeep = 0;
        if (tid < KSEL) {
            mykeep = sKeep[tid];
            int pi = sIdx[tid] / ef;
            const float* pr = parent + ((size_t)b * parentN + pi) * 4;
            float pcx = pr[0], pcy = pr[1], pw = pr[2], ph = pr[3];
            float px1 = (pcx - 0.5f * pw) * img_w;
            float py1 = (pcy - 0.5f * ph) * img_h;
            float px2 = (pcx + 0.5f * pw) * img_w;
            float py2 = (pcy + 0.5f * ph) * img_h;
            float bx1 = sBox[tid * 4 + 0], by1 = sBox[tid * 4 + 1];
            float bx2 = sBox[tid * 4 + 2], by2 = sBox[tid * 4 + 3];
            float ix1 = fmaxf(bx1, px1), iy1 = fmaxf(by1, py1);
            float ix2 = fminf(bx2, px2), iy2 = fminf(by2, py2);
            float inter = fmaxf(ix2 - ix1, 0.0f) * fmaxf(iy2 - iy1, 0.0f);
            float carea = (bx2 - bx1) * (by2 - by1);
            float belong = inter / (carea + 1e-6f);
            sBelong[tid] = belong;
            valid = (belong > 0.6f) ? 1 : 0;
        }
        int haveValid = __syncthreads_or(valid && mykeep);
        if (!haveValid) {
            if (tid == 0) {
                float best = -INFINITY; int bi = 0;
                for (int kk = 0; kk < KSEL; kk++) {
                    float v = sKeep[kk] ? sBelong[kk] : -INFINITY;
                    if (v > best) { best = v; bi = kk; }
                }
                sFb = bi;
            }
            __syncthreads();
            if (tid < KSEL) valid = (tid == sFb) ? 1 : 0;
        }
        if (tid < KSEL) sKeep[tid] &= valid;
    }
    __syncthreads();

    // ---- 9. greedy NMS: warp 0, register-resident, no block barriers ----
    if (tid < 32) {
        float x1r[4], y1r[4], x2r[4], y2r[4], arr[4]; int kp[4];
        #pragma unroll
        for (int s = 0; s < 4; s++) {
            int idx = tid + 32 * s;
            if (idx < KSEL) {
                x1r[s] = sBox[idx * 4 + 0]; y1r[s] = sBox[idx * 4 + 1];
                x2r[s] = sBox[idx * 4 + 2]; y2r[s] = sBox[idx * 4 + 3];
                arr[s] = sArea[idx];        kp[s]  = sKeep[idx];
            } else {
                x1r[s] = 0.f; y1r[s] = 0.f; x2r[s] = 0.f; y2r[s] = 0.f;
                arr[s] = 0.f; kp[s] = 0;
            }
        }
        #pragma unroll
        for (int slot = 0; slot < 4; slot++) {
            const int lim = (slot < 3) ? 32 : (KSEL - 96);
            for (int o = 0; o < lim; o++) {
                int   ki  = __shfl_sync(0xffffffffu, kp[slot],  o);
                float ix1 = __shfl_sync(0xffffffffu, x1r[slot], o);
                float iy1 = __shfl_sync(0xffffffffu, y1r[slot], o);
                float ix2 = __shfl_sync(0xffffffffu, x2r[slot], o);
                float iy2 = __shfl_sync(0xffffffffu, y2r[slot], o);
                float iar = __shfl_sync(0xffffffffu, arr[slot], o);
                if (ki) {
                    int i = slot * 32 + o;
                    #pragma unroll
                    for (int s = 0; s < 4; s++) {
                        int idx = tid + 32 * s;
                        if (idx > i && idx < KSEL && kp[s]) {
                            float tx1 = fmaxf(ix1, x1r[s]);
                            float ty1 = fmaxf(iy1, y1r[s]);
                            float tx2 = fminf(ix2, x2r[s]);
                            float ty2 = fminf(iy2, y2r[s]);
                            float inter = fmaxf(tx2 - tx1, 0.0f) * fmaxf(ty2 - ty1, 0.0f);
                            float iou = inter / (iar + arr[s] - inter);
                            if (iou > 0.1f) kp[s] = 0;
                        }
                    }
                }
            }
        }
        #pragma unroll
        for (int s = 0; s < 4; s++) {
            int idx = tid + 32 * s;
            if (idx < KSEL) sKeep[idx] = kp[s];
        }
    }
    __syncthreads();

    // ---- 10. write outputs ----
    if (tid < KSEL) {
        const int nk = sKeep[tid];
        for (int j = 0; j < dd; j++)
            out[data_off + ((size_t)b * KSEL + tid) * dd + j] =
                nk ? sData[tid * 16 + j] : 0.0f;
        out[score_off + (size_t)b * KSEL + tid] = nk ? sVal[tid] : 0.0f;
        out[keep_off  + (size_t)b * KSEL + tid] = nk ? 1.0f : 0.0f;
    }
}

extern "C" void kernel_launch(void* const* d_in, const int* in_sizes, int n_in,
                              void* d_out, int out_size) {
    const float* blk_logits = (const float*)d_in[0];
    const float* lin_logits = (const float*)d_in[1];
    const float* chr_logits = (const float*)d_in[2];
    const float* blk_raw    = (const float*)d_in[3];
    const float* lin_raw    = (const float*)d_in[4];
    const float* chr_raw    = (const float*)d_in[5];
    const float* tsizes     = (const float*)d_in[6];
    float* out = (float*)d_out;

    const int smem = 16384 * sizeof(uint32_t);   // 64 KB
    cudaFuncSetAttribute(postprocess_kernel,
                         cudaFuncAttributeMaxDynamicSharedMemorySize, smem);
    dim3 grid(64, 3);
    postprocess_kernel<<<grid, NTHREADS, smem>>>(
        blk_logits, lin_logits, chr_logits,
        blk_raw, lin_raw, chr_raw, tsizes, out);
}

// round 10
// speedup vs baseline: 1.3628x; 1.0511x over previous
#include <cuda_runtime.h>
#include <cstdint>
#include <math.h>

#define KSEL 100
#define NTHREADS 512
#define NWARPS (NTHREADS / 32)
#define CAND_MAX 512
#define EPT 32              // max elements per thread (16384 / 512)
#define SAMPLE_NUM 10

__device__ __forceinline__ uint32_t f2key(float f) {
    uint32_t u = __float_as_uint(f);
    return (u & 0x80000000u) ? ~u : (u | 0x80000000u);
}

__global__ __launch_bounds__(NTHREADS) void postprocess_kernel(
    const float* __restrict__ blk_logits,
    const float* __restrict__ lin_logits,
    const float* __restrict__ chr_logits,
    const float* __restrict__ blk_raw,
    const float* __restrict__ lin_raw,
    const float* __restrict__ chr_raw,
    const float* __restrict__ tsizes,
    float* __restrict__ out)
{
    __shared__ int       sPart[2][NWARPS];
    __shared__ unsigned long long sCand[CAND_MAX];
    __shared__ int       sCandCnt;
    __shared__ float     sVal[KSEL];
    __shared__ int       sIdx[KSEL];
    __shared__ float     sData[KSEL * 16];
    __shared__ float     sBox[KSEL * 4];
    __shared__ float     sArea[KSEL];
    __shared__ int       sKeep[KSEL];
    __shared__ float     sBelong[KSEL];
    __shared__ int       sFb;

    const int b     = blockIdx.x;
    const int level = blockIdx.y;
    const int tid   = threadIdx.x;
    const int lane  = tid & 31;
    const int wid   = tid >> 5;

    const float* logits;
    const float* raw;
    const float* parent = nullptr;
    int N, parentN = 0, ef = 1;
    bool bez = false;
    int data_off, score_off, keep_off, dd;

    if (level == 0) {
        logits = blk_logits; raw = blk_raw; N = 4096; dd = 4;
        data_off = 0;      score_off = 25600;  keep_off = 32000;
    } else if (level == 1) {
        logits = lin_logits; raw = lin_raw; parent = blk_raw; parentN = 4096; ef = 4;
        N = 16384; dd = 4;
        data_off = 38400;  score_off = 64000;  keep_off = 70400;
    } else {
        logits = chr_logits; raw = chr_raw; parent = lin_raw; parentN = 16384; ef = 1;
        N = 16384; dd = 16; bez = true;
        data_off = 76800;  score_off = 179200; keep_off = 185600;
    }

    const float img_h = tsizes[2 * b + 0];
    const float img_w = tsizes[2 * b + 1];
    const float* lg = logits + (size_t)b * N;

    // ---- 1. load keys into registers (coalesced float4, high MLP) ----
    const float4* lg4 = (const float4*)lg;
    const int N4 = N >> 2;                 // 1024 or 4096
    uint32_t kreg[EPT];
    #pragma unroll
    for (int j = 0; j < 8; j++) {
        int i4 = tid + NTHREADS * j;
        if (i4 < N4) {
            float4 v = lg4[i4];
            kreg[4 * j + 0] = f2key(v.x);
            kreg[4 * j + 1] = f2key(v.y);
            kreg[4 * j + 2] = f2key(v.z);
            kreg[4 * j + 3] = f2key(v.w);
        } else {
            kreg[4 * j + 0] = 0u; kreg[4 * j + 1] = 0u;
            kreg[4 * j + 2] = 0u; kreg[4 * j + 3] = 0u;
        }
    }
    if (tid == 0) sCandCnt = 0;

    // ---- 2. bisection on u32 key space: find T with count_ge(T) in [100,512] ----
    uint32_t lo = 0u, hi = 0xFFFFFFFFu, T = 0u;
    for (int it = 0; it < 34; it++) {
        uint32_t mid = lo + ((hi - lo) >> 1);
        int c = 0;
        #pragma unroll
        for (int e = 0; e < EPT; e++) c += (kreg[e] >= mid) ? 1 : 0;
        #pragma unroll
        for (int d = 16; d > 0; d >>= 1)
            c += __shfl_down_sync(0xffffffffu, c, d);
        if (lane == 0) sPart[it & 1][wid] = c;
        __syncthreads();
        int tot = 0;
        #pragma unroll
        for (int w = 0; w < NWARPS; w++) tot += sPart[it & 1][w];
        if (tot >= KSEL && tot <= CAND_MAX) { T = mid; break; }
        if (tot > CAND_MAX) lo = mid; else hi = mid;
        if (hi - lo <= 1u) { T = lo; break; }   // >412 exact dup ties: ~impossible
    }

    // ---- 3. collect candidates >= T from registers ----
    #pragma unroll
    for (int e = 0; e < EPT; e++) {
        if (kreg[e] >= T) {
            int gi = 4 * (tid + NTHREADS * (e >> 2)) + (e & 3);
            int pos = atomicAdd(&sCandCnt, 1);
            if (pos < CAND_MAX)
                sCand[pos] = ~(((unsigned long long)kreg[e] << 32) |
                               (unsigned long long)(0xFFFFFFFFu - (uint32_t)gi));
        }
    }
    __syncthreads();
    const int cnt = min(sCandCnt, CAND_MAX);
    int M2 = 128;
    while (M2 < cnt) M2 <<= 1;                          // 128 / 256 / 512
    for (int i = cnt + tid; i < M2; i += NTHREADS)
        sCand[i] = 0xFFFFFFFFFFFFFFFFull;               // sorts last
    __syncthreads();

    // ---- 4. bitonic sort M2 elements ascending ----
    for (int size2 = 2; size2 <= M2; size2 <<= 1) {
        for (int stride = size2 >> 1; stride > 0; stride >>= 1) {
            if (tid < (M2 >> 1)) {
                int pos = ((tid & ~(stride - 1)) << 1) | (tid & (stride - 1));
                bool up = ((pos & size2) == 0);
                unsigned long long a = sCand[pos];
                unsigned long long c = sCand[pos + stride];
                if ((a > c) == up) { sCand[pos] = c; sCand[pos + stride] = a; }
            }
            __syncthreads();
        }
    }

    // ---- 5. decode top-100 ----
    if (tid < KSEL) {
        unsigned long long comb = ~sCand[tid];
        uint32_t kk  = (uint32_t)(comb >> 32);
        uint32_t idx = 0xFFFFFFFFu - (uint32_t)(comb & 0xFFFFFFFFull);
        sIdx[tid] = (int)idx;
        uint32_t u = (kk & 0x80000000u) ? (kk & 0x7FFFFFFFu) : ~kk;
        float lv = __uint_as_float(u);
        sVal[tid] = 1.0f / (1.0f + expf(-lv));
    }
    __syncthreads();

    // ---- 6. boxes / data ----
    if (tid < KSEL) {
        int si = sIdx[tid];
        if (!bez) {
            const float* r = raw + ((size_t)b * N + si) * 4;
            float cx = r[0], cy = r[1], w = r[2], h = r[3];
            float x1 = (cx - 0.5f * w) * img_w;
            float y1 = (cy - 0.5f * h) * img_h;
            float x2 = (cx + 0.5f * w) * img_w;
            float y2 = (cy + 0.5f * h) * img_h;
            if (level == 0) {
                x1 = fminf(fmaxf(x1, 0.0f), img_w);
                y1 = fminf(fmaxf(y1, 0.0f), img_h);
                x2 = fminf(fmaxf(x2, 0.0f), img_w);
                y2 = fminf(fmaxf(y2, 0.0f), img_h);
            }
            sData[tid * 16 + 0] = x1; sData[tid * 16 + 1] = y1;
            sData[tid * 16 + 2] = x2; sData[tid * 16 + 3] = y2;
            sBox[tid * 4 + 0] = x1; sBox[tid * 4 + 1] = y1;
            sBox[tid * 4 + 2] = x2; sBox[tid * 4 + 3] = y2;
            sArea[tid] = (x2 - x1) * (y2 - y1);
        } else {
            const float* r = raw + ((size_t)b * N + si) * 16;
            float cp0[8], cp1[8];
            #pragma unroll
            for (int f = 0; f < 8; f++) {
                cp0[f] = r[2 * f + 0] * img_h;          // scale_pts = tile((h,w),8)
                cp1[f] = r[2 * f + 1] * img_w;
                sData[tid * 16 + 2 * f + 0] = cp0[f];
                sData[tid * 16 + 2 * f + 1] = cp1[f];
            }
            float mn0 =  INFINITY, mn1 =  INFINITY;
            float mx0 = -INFINITY, mx1 = -INFINITY;
            #pragma unroll
            for (int s = 0; s < SAMPLE_NUM; s++) {
                float t  = (float)s / (float)(SAMPLE_NUM - 1);
                float ti = 1.0f - t;
                float b0c = ti * ti * ti;
                float b1c = 3.0f * t * ti * ti;
                float b2c = 3.0f * t * t * ti;
                float b3c = t * t * t;
                float px = b0c * cp0[0] + b1c * cp0[1] + b2c * cp0[2] + b3c * cp0[3];
                float py = b0c * cp1[0] + b1c * cp1[1] + b2c * cp1[2] + b3c * cp1[3];
                float qx = b0c * cp0[4] + b1c * cp0[5] + b2c * cp0[6] + b3c * cp0[7];
                float qy = b0c * cp1[4] + b1c * cp1[5] + b2c * cp1[6] + b3c * cp1[7];
                mn0 = fminf(mn0, fminf(px, qx));
                mn1 = fminf(mn1, fminf(py, qy));
                mx0 = fmaxf(mx0, fmaxf(px, qx));
                mx1 = fmaxf(mx1, fmaxf(py, qy));
            }
            sBox[tid * 4 + 0] = mn0; sBox[tid * 4 + 1] = mn1;
            sBox[tid * 4 + 2] = mx0; sBox[tid * 4 + 3] = mx1;
            sArea[tid] = (mx0 - mn0) * (mx1 - mn1);
        }
    }

    // ---- 7. keep = vals > 0.1 (fallback to index 0) ----
    int keep0 = (tid < KSEL) ? (sVal[tid] > 0.1f ? 1 : 0) : 0;
    int any0 = __syncthreads_or(keep0);
    if (tid < KSEL) sKeep[tid] = any0 ? keep0 : (tid == 0 ? 1 : 0);

    // ---- 8. parent belong filter (line / char) ----
    if (level > 0) {
        int valid = 0, mykeep = 0;
        if (tid < KSEL) {
            mykeep = sKeep[tid];
            int pi = sIdx[tid] / ef;
            const float* pr = parent + ((size_t)b * parentN + pi) * 4;
            float pcx = pr[0], pcy = pr[1], pw = pr[2], ph = pr[3];
            float px1 = (pcx - 0.5f * pw) * img_w;
            float py1 = (pcy - 0.5f * ph) * img_h;
            float px2 = (pcx + 0.5f * pw) * img_w;
            float py2 = (pcy + 0.5f * ph) * img_h;
            float bx1 = sBox[tid * 4 + 0], by1 = sBox[tid * 4 + 1];
            float bx2 = sBox[tid * 4 + 2], by2 = sBox[tid * 4 + 3];
            float ix1 = fmaxf(bx1, px1), iy1 = fmaxf(by1, py1);
            float ix2 = fminf(bx2, px2), iy2 = fminf(by2, py2);
            float inter = fmaxf(ix2 - ix1, 0.0f) * fmaxf(iy2 - iy1, 0.0f);
            float carea = (bx2 - bx1) * (by2 - by1);
            float belong = inter / (carea + 1e-6f);
            sBelong[tid] = belong;
            valid = (belong > 0.6f) ? 1 : 0;
        }
        int haveValid = __syncthreads_or(valid && mykeep);
        if (!haveValid) {
            if (tid == 0) {
                float best = -INFINITY; int bi = 0;
                for (int kk = 0; kk < KSEL; kk++) {
                    float v = sKeep[kk] ? sBelong[kk] : -INFINITY;
                    if (v > best) { best = v; bi = kk; }
                }
                sFb = bi;
            }
            __syncthreads();
            if (tid < KSEL) valid = (tid == sFb) ? 1 : 0;
        }
        if (tid < KSEL) sKeep[tid] &= valid;
    }
    __syncthreads();

    // ---- 9. greedy NMS: warp 0, register-resident, no block barriers ----
    if (tid < 32) {
        float x1r[4], y1r[4], x2r[4], y2r[4], arr[4]; int kp[4];
        #pragma unroll
        for (int s = 0; s < 4; s++) {
            int idx = tid + 32 * s;
            if (idx < KSEL) {
                x1r[s] = sBox[idx * 4 + 0]; y1r[s] = sBox[idx * 4 + 1];
                x2r[s] = sBox[idx * 4 + 2]; y2r[s] = sBox[idx * 4 + 3];
                arr[s] = sArea[idx];        kp[s]  = sKeep[idx];
            } else {
                x1r[s] = 0.f; y1r[s] = 0.f; x2r[s] = 0.f; y2r[s] = 0.f;
                arr[s] = 0.f; kp[s] = 0;
            }
        }
        #pragma unroll
        for (int slot = 0; slot < 4; slot++) {
            const int lim = (slot < 3) ? 32 : (KSEL - 96);
            for (int o = 0; o < lim; o++) {
                int   ki  = __shfl_sync(0xffffffffu, kp[slot],  o);
                float ix1 = __shfl_sync(0xffffffffu, x1r[slot], o);
                float iy1 = __shfl_sync(0xffffffffu, y1r[slot], o);
                float ix2 = __shfl_sync(0xffffffffu, x2r[slot], o);
                float iy2 = __shfl_sync(0xffffffffu, y2r[slot], o);
                float iar = __shfl_sync(0xffffffffu, arr[slot], o);
                if (ki) {
                    int i = slot * 32 + o;
                    #pragma unroll
                    for (int s = 0; s < 4; s++) {
                        int idx = tid + 32 * s;
                        if (idx > i && idx < KSEL && kp[s]) {
                            float tx1 = fmaxf(ix1, x1r[s]);
                            float ty1 = fmaxf(iy1, y1r[s]);
                            float tx2 = fminf(ix2, x2r[s]);
                            float ty2 = fminf(iy2, y2r[s]);
                            float inter = fmaxf(tx2 - tx1, 0.0f) * fmaxf(ty2 - ty1, 0.0f);
                            float iou = inter / (iar + arr[s] - inter);
                            if (iou > 0.1f) kp[s] = 0;
                        }
                    }
                }
            }
        }
        #pragma unroll
        for (int s = 0; s < 4; s++) {
            int idx = tid + 32 * s;
            if (idx < KSEL) sKeep[idx] = kp[s];
        }
    }
    __syncthreads();

    // ---- 10. write outputs ----
    if (tid < KSEL) {
        const int nk = sKeep[tid];
        for (int j = 0; j < dd; j++)
            out[data_off + ((size_t)b * KSEL + tid) * dd + j] =
                nk ? sData[tid * 16 + j] : 0.0f;
        out[score_off + (size_t)b * KSEL + tid] = nk ? sVal[tid] : 0.0f;
        out[keep_off  + (size_t)b * KSEL + tid] = nk ? 1.0f : 0.0f;
    }
}

extern "C" void kernel_launch(void* const* d_in, const int* in_sizes, int n_in,
                              void* d_out, int out_size) {
    const float* blk_logits = (const float*)d_in[0];
    const float* lin_logits = (const float*)d_in[1];
    const float* chr_logits = (const float*)d_in[2];
    const float* blk_raw    = (const float*)d_in[3];
    const float* lin_raw    = (const float*)d_in[4];
    const float* chr_raw    = (const float*)d_in[5];
    const float* tsizes     = (const float*)d_in[6];
    float* out = (float*)d_out;

    dim3 grid(64, 3);
    postprocess_kernel<<<grid, NTHREADS>>>(
        blk_logits, lin_logits, chr_logits,
        blk_raw, lin_raw, chr_raw, tsizes, out);
}

// round 12
// speedup vs baseline: 1.6960x; 1.2444x over previous
#include <cuda_runtime.h>
#include <cstdint>
#include <math.h>

#define KSEL 100
#define NTHREADS 512
#define NWARPS (NTHREADS / 32)
#define CAND_MAX 512
#define SAMPLE_NUM 10

__device__ __forceinline__ uint32_t f2key(float f) {
    uint32_t u = __float_as_uint(f);
    return (u & 0x80000000u) ? ~u : (u | 0x80000000u);
}

__global__ __launch_bounds__(NTHREADS) void postprocess_kernel(
    const float* __restrict__ blk_logits,
    const float* __restrict__ lin_logits,
    const float* __restrict__ chr_logits,
    const float* __restrict__ blk_raw,
    const float* __restrict__ lin_raw,
    const float* __restrict__ chr_raw,
    const float* __restrict__ tsizes,
    float* __restrict__ out)
{
    __shared__ int       sPart[2][NWARPS];
    __shared__ unsigned long long sCand[CAND_MAX];
    __shared__ int       sCandCnt;
    __shared__ float     sVal[KSEL];
    __shared__ int       sIdx[KSEL];
    __shared__ float     sData[KSEL * 16];
    __shared__ float     sBox[KSEL * 4];
    __shared__ float     sArea[KSEL];
    __shared__ int       sKeep[KSEL];
    __shared__ float     sBelong[KSEL];
    __shared__ int       sFb;

    const int b     = blockIdx.x;
    const int level = blockIdx.y;
    const int tid   = threadIdx.x;
    const int lane  = tid & 31;
    const int wid   = tid >> 5;

    const float* logits;
    const float* raw;
    const float* parent = nullptr;
    int N, parentN = 0, ef = 1;
    bool bez = false;
    int data_off, score_off, keep_off, dd;
    float t0f;

    if (level == 0) {
        logits = blk_logits; raw = blk_raw; N = 4096; dd = 4;
        data_off = 0;      score_off = 25600;  keep_off = 32000;
        t0f = 1.60f;                       // E[count]≈224 of 4096
    } else if (level == 1) {
        logits = lin_logits; raw = lin_raw; parent = blk_raw; parentN = 4096; ef = 4;
        N = 16384; dd = 4;
        data_off = 38400;  score_off = 64000;  keep_off = 70400;
        t0f = 2.15f;                       // E[count]≈259 of 16384
    } else {
        logits = chr_logits; raw = chr_raw; parent = lin_raw; parentN = 16384; ef = 1;
        N = 16384; dd = 16; bez = true;
        data_off = 76800;  score_off = 179200; keep_off = 185600;
        t0f = 2.15f;
    }
    const uint32_t T0 = f2key(t0f);

    const float img_h = tsizes[2 * b + 0];
    const float img_w = tsizes[2 * b + 1];
    const float* lg = logits + (size_t)b * N;
    const float4* lg4 = (const float4*)lg;
    const int N4 = N >> 2;                 // 1024 or 4096

    if (tid == 0) sCandCnt = 0;
    __syncthreads();

    // ---- 1. fused load + threshold + collect (single pass, batched LDGs) ----
    {
        float4 vreg[8];
        #pragma unroll
        for (int j = 0; j < 8; j++) {
            int i4 = tid + NTHREADS * j;
            vreg[j] = (i4 < N4) ? lg4[i4]
                                : make_float4(-1e30f, -1e30f, -1e30f, -1e30f);
        }
        #pragma unroll
        for (int j = 0; j < 8; j++) {
            int i4 = tid + NTHREADS * j;
            float e[4] = {vreg[j].x, vreg[j].y, vreg[j].z, vreg[j].w};
            #pragma unroll
            for (int q = 0; q < 4; q++) {
                uint32_t kk = f2key(e[q]);
                if (kk >= T0 && i4 < N4) {
                    int gi = 4 * i4 + q;
                    int pos = atomicAdd(&sCandCnt, 1);
                    if (pos < CAND_MAX)
                        sCand[pos] = ~(((unsigned long long)kk << 32) |
                                       (unsigned long long)(0xFFFFFFFFu - (uint32_t)gi));
                }
            }
        }
    }
    __syncthreads();
    int cnt = sCandCnt;

    // ---- 2. fallback (uniform branch, ~never taken on real data) ----
    if (cnt < KSEL || cnt > CAND_MAX) {
        uint32_t lo = 0u, hi = 0xFFFFFFFFu, T = 0u;
        for (int it = 0; it < 34; it++) {
            uint32_t mid = lo + ((hi - lo) >> 1);
            int c = 0;
            #pragma unroll
            for (int j = 0; j < 8; j++) {
                int i4 = tid + NTHREADS * j;
                if (i4 < N4) {
                    float4 v = lg4[i4];
                    c += (f2key(v.x) >= mid) + (f2key(v.y) >= mid)
                       + (f2key(v.z) >= mid) + (f2key(v.w) >= mid);
                }
            }
            #pragma unroll
            for (int d = 16; d > 0; d >>= 1)
                c += __shfl_down_sync(0xffffffffu, c, d);
            if (lane == 0) sPart[it & 1][wid] = c;
            __syncthreads();
            int tot = 0;
            #pragma unroll
            for (int w = 0; w < NWARPS; w++) tot += sPart[it & 1][w];
            if (tot >= KSEL && tot <= CAND_MAX) { T = mid; break; }
            if (tot > CAND_MAX) lo = mid; else hi = mid;
            if (hi - lo <= 1u) { T = lo; break; }
        }
        if (tid == 0) sCandCnt = 0;
        __syncthreads();
        #pragma unroll
        for (int j = 0; j < 8; j++) {
            int i4 = tid + NTHREADS * j;
            if (i4 < N4) {
                float4 v = lg4[i4];
                float e[4] = {v.x, v.y, v.z, v.w};
                #pragma unroll
                for (int q = 0; q < 4; q++) {
                    uint32_t kk = f2key(e[q]);
                    if (kk >= T) {
                        int gi = 4 * i4 + q;
                        int pos = atomicAdd(&sCandCnt, 1);
                        if (pos < CAND_MAX)
                            sCand[pos] = ~(((unsigned long long)kk << 32) |
                                           (unsigned long long)(0xFFFFFFFFu - (uint32_t)gi));
                    }
                }
            }
        }
        __syncthreads();
        cnt = min(sCandCnt, CAND_MAX);
    }

    // ---- 3. enumeration sort: rank & scatter top-100 (1 barrier) ----
    if (tid < KSEL) { sVal[tid] = 0.0f; sIdx[tid] = 0; }
    __syncthreads();
    if (tid < cnt) {
        unsigned long long mine = sCand[tid];
        int rank = 0;
        int j = 0;
        for (; j + 3 < cnt; j += 4)
            rank += (sCand[j]     < mine) + (sCand[j + 1] < mine)
                  + (sCand[j + 2] < mine) + (sCand[j + 3] < mine);
        for (; j < cnt; j++) rank += (sCand[j] < mine);
        if (rank < KSEL) {
            unsigned long long comb = ~mine;
            uint32_t kk  = (uint32_t)(comb >> 32);
            uint32_t idx = 0xFFFFFFFFu - (uint32_t)(comb & 0xFFFFFFFFull);
            sIdx[rank] = (int)idx;
            uint32_t u = (kk & 0x80000000u) ? (kk & 0x7FFFFFFFu) : ~kk;
            float lv = __uint_as_float(u);
            sVal[rank] = 1.0f / (1.0f + expf(-lv));
        }
    }
    __syncthreads();

    // ---- 4. boxes / data ----
    if (tid < KSEL) {
        int si = sIdx[tid];
        if (!bez) {
            const float* r = raw + ((size_t)b * N + si) * 4;
            float cx = r[0], cy = r[1], w = r[2], h = r[3];
            float x1 = (cx - 0.5f * w) * img_w;
            float y1 = (cy - 0.5f * h) * img_h;
            float x2 = (cx + 0.5f * w) * img_w;
            float y2 = (cy + 0.5f * h) * img_h;
            if (level == 0) {
                x1 = fminf(fmaxf(x1, 0.0f), img_w);
                y1 = fminf(fmaxf(y1, 0.0f), img_h);
                x2 = fminf(fmaxf(x2, 0.0f), img_w);
                y2 = fminf(fmaxf(y2, 0.0f), img_h);
            }
            sData[tid * 16 + 0] = x1; sData[tid * 16 + 1] = y1;
            sData[tid * 16 + 2] = x2; sData[tid * 16 + 3] = y2;
            sBox[tid * 4 + 0] = x1; sBox[tid * 4 + 1] = y1;
            sBox[tid * 4 + 2] = x2; sBox[tid * 4 + 3] = y2;
            sArea[tid] = (x2 - x1) * (y2 - y1);
        } else {
            const float* r = raw + ((size_t)b * N + si) * 16;
            float cp0[8], cp1[8];
            #pragma unroll
            for (int f = 0; f < 8; f++) {
                cp0[f] = r[2 * f + 0] * img_h;          // scale_pts = tile((h,w),8)
                cp1[f] = r[2 * f + 1] * img_w;
                sData[tid * 16 + 2 * f + 0] = cp0[f];
                sData[tid * 16 + 2 * f + 1] = cp1[f];
            }
            float mn0 =  INFINITY, mn1 =  INFINITY;
            float mx0 = -INFINITY, mx1 = -INFINITY;
            #pragma unroll
            for (int s = 0; s < SAMPLE_NUM; s++) {
                float t  = (float)s / (float)(SAMPLE_NUM - 1);
                float ti = 1.0f - t;
                float b0c = ti * ti * ti;
                float b1c = 3.0f * t * ti * ti;
                float b2c = 3.0f * t * t * ti;
                float b3c = t * t * t;
                float px = b0c * cp0[0] + b1c * cp0[1] + b2c * cp0[2] + b3c * cp0[3];
                float py = b0c * cp1[0] + b1c * cp1[1] + b2c * cp1[2] + b3c * cp1[3];
                float qx = b0c * cp0[4] + b1c * cp0[5] + b2c * cp0[6] + b3c * cp0[7];
                float qy = b0c * cp1[4] + b1c * cp1[5] + b2c * cp1[6] + b3c * cp1[7];
                mn0 = fminf(mn0, fminf(px, qx));
                mn1 = fminf(mn1, fminf(py, qy));
                mx0 = fmaxf(mx0, fmaxf(px, qx));
                mx1 = fmaxf(mx1, fmaxf(py, qy));
            }
            sBox[tid * 4 + 0] = mn0; sBox[tid * 4 + 1] = mn1;
            sBox[tid * 4 + 2] = mx0; sBox[tid * 4 + 3] = mx1;
            sArea[tid] = (mx0 - mn0) * (mx1 - mn1);
        }
    }

    // ---- 5. keep = vals > 0.1 (fallback to index 0) ----
    int keep0 = (tid < KSEL) ? (sVal[tid] > 0.1f ? 1 : 0) : 0;
    int any0 = __syncthreads_or(keep0);
    if (tid < KSEL) sKeep[tid] = any0 ? keep0 : (tid == 0 ? 1 : 0);

    // ---- 6. parent belong filter (line / char) ----
    if (level > 0) {
        int valid = 0, mykeep = 0;
        if (tid < KSEL) {
            mykeep = sKeep[tid];
            int pi = sIdx[tid] / ef;
            const float* pr = parent + ((size_t)b * parentN + pi) * 4;
            float pcx = pr[0], pcy = pr[1], pw = pr[2], ph = pr[3];
            float px1 = (pcx - 0.5f * pw) * img_w;
            float py1 = (pcy - 0.5f * ph) * img_h;
            float px2 = (pcx + 0.5f * pw) * img_w;
            float py2 = (pcy + 0.5f * ph) * img_h;
            float bx1 = sBox[tid * 4 + 0], by1 = sBox[tid * 4 + 1];
            float bx2 = sBox[tid * 4 + 2], by2 = sBox[tid * 4 + 3];
            float ix1 = fmaxf(bx1, px1), iy1 = fmaxf(by1, py1);
            float ix2 = fminf(bx2, px2), iy2 = fminf(by2, py2);
            float inter = fmaxf(ix2 - ix1, 0.0f) * fmaxf(iy2 - iy1, 0.0f);
            float carea = (bx2 - bx1) * (by2 - by1);
            float belong = inter / (carea + 1e-6f);
            sBelong[tid] = belong;
            valid = (belong > 0.6f) ? 1 : 0;
        }
        int haveValid = __syncthreads_or(valid && mykeep);
        if (!haveValid) {
            if (tid == 0) {
                float best = -INFINITY; int bi = 0;
                for (int kk = 0; kk < KSEL; kk++) {
                    float v = sKeep[kk] ? sBelong[kk] : -INFINITY;
                    if (v > best) { best = v; bi = kk; }
                }
                sFb = bi;
            }
            __syncthreads();
            if (tid < KSEL) valid = (tid == sFb) ? 1 : 0;
        }
        if (tid < KSEL) sKeep[tid] &= valid;
    }
    __syncthreads();

    // ---- 7. greedy NMS: warp 0, register-resident, no block barriers ----
    if (tid < 32) {
        float x1r[4], y1r[4], x2r[4], y2r[4], arr[4]; int kp[4];
        #pragma unroll
        for (int s = 0; s < 4; s++) {
            int idx = tid + 32 * s;
            if (idx < KSEL) {
                x1r[s] = sBox[idx * 4 + 0]; y1r[s] = sBox[idx * 4 + 1];
                x2r[s] = sBox[idx * 4 + 2]; y2r[s] = sBox[idx * 4 + 3];
                arr[s] = sArea[idx];        kp[s]  = sKeep[idx];
            } else {
                x1r[s] = 0.f; y1r[s] = 0.f; x2r[s] = 0.f; y2r[s] = 0.f;
                arr[s] = 0.f; kp[s] = 0;
            }
        }
        #pragma unroll
        for (int slot = 0; slot < 4; slot++) {
            const int lim = (slot < 3) ? 32 : (KSEL - 96);
            for (int o = 0; o < lim; o++) {
                int   ki  = __shfl_sync(0xffffffffu, kp[slot],  o);
                float ix1 = __shfl_sync(0xffffffffu, x1r[slot], o);
                float iy1 = __shfl_sync(0xffffffffu, y1r[slot], o);
                float ix2 = __shfl_sync(0xffffffffu, x2r[slot], o);
                float iy2 = __shfl_sync(0xffffffffu, y2r[slot], o);
                float iar = __shfl_sync(0xffffffffu, arr[slot], o);
                if (ki) {
                    int i = slot * 32 + o;
                    #pragma unroll
                    for (int s = 0; s < 4; s++) {
                        int idx = tid + 32 * s;
                        if (idx > i && idx < KSEL && kp[s]) {
                            float tx1 = fmaxf(ix1, x1r[s]);
                            float ty1 = fmaxf(iy1, y1r[s]);
                            float tx2 = fminf(ix2, x2r[s]);
                            float ty2 = fminf(iy2, y2r[s]);
                            float inter = fmaxf(tx2 - tx1, 0.0f) * fmaxf(ty2 - ty1, 0.0f);
                            float iou = inter / (iar + arr[s] - inter);
                            if (iou > 0.1f) kp[s] = 0;
                        }
                    }
                }
            }
        }
        #pragma unroll
        for (int s = 0; s < 4; s++) {
            int idx = tid + 32 * s;
            if (idx < KSEL) sKeep[idx] = kp[s];
        }
    }
    __syncthreads();

    // ---- 8. write outputs ----
    if (tid < KSEL) {
        const int nk = sKeep[tid];
        for (int j = 0; j < dd; j++)
            out[data_off + ((size_t)b * KSEL + tid) * dd + j] =
                nk ? sData[tid * 16 + j] : 0.0f;
        out[score_off + (size_t)b * KSEL + tid] = nk ? sVal[tid] : 0.0f;
        out[keep_off  + (size_t)b * KSEL + tid] = nk ? 1.0f : 0.0f;
    }
}

extern "C" void kernel_launch(void* const* d_in, const int* in_sizes, int n_in,
                              void* d_out, int out_size) {
    const float* blk_logits = (const float*)d_in[0];
    const float* lin_logits = (const float*)d_in[1];
    const float* chr_logits = (const float*)d_in[2];
    const float* blk_raw    = (const float*)d_in[3];
    const float* lin_raw    = (const float*)d_in[4];
    const float* chr_raw    = (const float*)d_in[5];
    const float* tsizes     = (const float*)d_in[6];
    float* out = (float*)d_out;

    dim3 grid(64, 3);
    postprocess_kernel<<<grid, NTHREADS>>>(
        blk_logits, lin_logits, chr_logits,
        blk_raw, lin_raw, chr_raw, tsizes, out);
}